// round 10
// baseline (speedup 1.0000x reference)
#include <cuda_runtime.h>
#include <math.h>

// Problem constants
static constexpr int IW = 1024;
static constexpr int IH = 1024;
static constexpr int NB = 16;
static constexpr int IMG = IW * IH;           // 1<<20
static constexpr int TOTAL = NB * IMG;        // 16M
static constexpr int NPASS = 12;
static constexpr int WPR = IW / 32;           // 32 words per row
static constexpr int WPI = IMG / 32;          // words per image

// Scratch (device globals: allocation-free rule)
__device__ float         g_thin[TOTAL];        // 64MB SQUARED thin magnitudes
__device__ unsigned int  g_sbits[TOTAL / 32];  // 2MB strong bitmap
__device__ unsigned int  g_wbits[TOTAL / 32];  // 2MB weak bitmap
__device__ unsigned int  g_magmax[NB];         // per-batch max squared mag, float bits
__device__ unsigned int  g_thinmax[NB];        // per-batch max squared thin, float bits
__device__ float2        g_thr[NB];            // per-batch squared-domain thresholds (hi, lo)
__device__ int           g_flags[NPASS];       // hysteresis per-pass "changed" flags

// ---------------------------------------------------------------- reset
__global__ void k_reset() {
    int t = threadIdx.x;
    if (t < NB) { g_magmax[t] = 0u; g_thinmax[t] = 0u; }
    if (t < NPASS) g_flags[t] = 0;
}

// ---------------------------------------------------------------- fused blur + sobel + NMS (squared domain)
// Tile: 64 rows x 32 cols per block, 256 threads.
__global__ void __launch_bounds__(256) k_main(const float* __restrict__ img) {
    __shared__ float         si[72][40];   // raw img, halo 4
    __shared__ float         hb[72][36];   // horizontal blur
    __shared__ float         sb[68][36];   // blurred, halo 2 (0 outside image = conv padding)
    __shared__ float         sm[66][34];   // SQUARED mag, halo 1 (0 outside image)
    __shared__ unsigned char sd[66][34];   // NMS axis code (interior only)
    __shared__ float red[16];
    const int b  = blockIdx.z;
    const int x0 = blockIdx.x * 32, y0 = blockIdx.y * 64;
    const float* im = img + (size_t)b * IMG;
    const int tid = threadIdx.x;

    const bool interior = (x0 >= 4) && (x0 + 36 <= IW) && (y0 >= 4) && (y0 + 68 <= IH);
    if (interior) {
        const float* base = im + (y0 - 4) * IW + (x0 - 4);
        for (int i = tid; i < 72 * 40; i += 256) {
            int r = i / 40, c = i % 40;
            si[r][c] = base[r * IW + c];
        }
    } else {
        for (int i = tid; i < 72 * 40; i += 256) {
            int r = i / 40, c = i % 40;
            int gy = y0 + r - 4, gx = x0 + c - 4;
            float v = 0.f;
            if ((unsigned)gy < (unsigned)IH && (unsigned)gx < (unsigned)IW) v = im[gy * IW + gx];
            si[r][c] = v;
        }
    }
    __syncthreads();

    // unnormalized gaussian window, sigma=1, K=5
    const float G0 = 0.13533528323661270231f;  // exp(-2)
    const float G1 = 0.60653065971263342360f;  // exp(-0.5)

    for (int i = tid; i < 72 * 36; i += 256) {
        int r = i / 36, c = i % 36;
        float v = G0 * si[r][c];
        v += G1 * si[r][c + 1];
        v += si[r][c + 2];
        v += G1 * si[r][c + 3];
        v += G0 * si[r][c + 4];
        hb[r][c] = v;
    }
    __syncthreads();

    for (int i = tid; i < 68 * 36; i += 256) {
        int r = i / 36, c = i % 36;
        int gy = y0 + r - 2, gx = x0 + c - 2;
        float v = 0.f;
        if ((unsigned)gy < (unsigned)IH && (unsigned)gx < (unsigned)IW) {
            v = G0 * hb[r][c];
            v += G1 * hb[r + 1][c];
            v += hb[r + 2][c];
            v += G1 * hb[r + 3][c];
            v += G0 * hb[r + 4][c];
        }
        sb[r][c] = v;
    }
    __syncthreads();

    const float T1 = 0.41421356237309503f;   // tan(22.5 deg)
    for (int i = tid; i < 66 * 34; i += 256) {
        int r = i / 34, c = i % 34;
        int gy = y0 + r - 1, gx = x0 + c - 1;
        float m = 0.f;
        unsigned char code = 0;
        if ((unsigned)gy < (unsigned)IH && (unsigned)gx < (unsigned)IW) {
            float a0 = sb[r][c],     a1 = sb[r][c + 1],     a2 = sb[r][c + 2];
            float b0 = sb[r + 1][c],                        b2 = sb[r + 1][c + 2];
            float c0 = sb[r + 2][c], c1 = sb[r + 2][c + 1], c2 = sb[r + 2][c + 2];
            float Ix = (a0 - a2) + 2.f * (b0 - b2) + (c0 - c2);
            float Iy = (a0 - c0) + 2.f * (a1 - c1) + (a2 - c2);
            m = Ix * Ix + Iy * Iy;     // squared magnitude (no sqrt)
            // Quantized NMS axis (only idx mod 4 matters; ties match round-half-even)
            float ax = fabsf(Ix), ay = fabsf(Iy);
            if (ay <= T1 * ax)      code = 0;                                   // E-W
            else if (ax <= T1 * ay) code = 1;                                   // N-S
            else if ((__float_as_int(Ix) ^ __float_as_int(Iy)) >= 0) code = 2;  // 45 deg
            else                    code = 3;                                   // 135 deg
        }
        sm[r][c] = m;
        sd[r][c] = code;
    }
    __syncthreads();

    const int cx = tid & 31;
    const int r0 = tid >> 5;
    float mmax = 0.f, tmax = 0.f;
    float* tp = g_thin + (size_t)b * IMG;

#pragma unroll
    for (int k = 0; k < 8; k++) {
        const int ry = r0 + 8 * k;
        const int r = ry + 1, c = cx + 1;
        float m = sm[r][c];
        int code = sd[r][c];
        int dy = (code == 0) ? 0 : 1;
        int dx = (code == 1) ? 0 : ((code == 3) ? -1 : 1);
        float n1 = sm[r + dy][c + dx];
        float n2 = sm[r - dy][c - dx];
        float thin = (m > n1 && m > n2) ? m : 0.f;
        tp[(y0 + ry) * IW + x0 + cx] = thin;
        mmax = fmaxf(mmax, m);
        tmax = fmaxf(tmax, thin);
    }

    for (int o = 16; o; o >>= 1) {
        mmax = fmaxf(mmax, __shfl_xor_sync(0xffffffffu, mmax, o));
        tmax = fmaxf(tmax, __shfl_xor_sync(0xffffffffu, tmax, o));
    }
    int warp = tid >> 5, lane = tid & 31;
    if (lane == 0) { red[warp] = mmax; red[warp + 8] = tmax; }
    __syncthreads();
    if (tid == 0) {
        float a = red[0], t2 = red[8];
        for (int w = 1; w < 8; w++) { a = fmaxf(a, red[w]); t2 = fmaxf(t2, red[w + 8]); }
        atomicMax(&g_magmax[b], __float_as_uint(a));
        atomicMax(&g_thinmax[b], __float_as_uint(t2));
    }
}

// ---------------------------------------------------------------- thresholds (exact, squared domain)
// sqrtf is correctly rounded & monotone: max(sqrt(s_i)) == sqrt(max s_i) bit-exact.
// Binary search inverts the EXACT predicate "sqrtf(s)/M >= thr" so classify
// compares are boolean-identical to the reference's divide-then-compare.
__global__ void k_hi() {
    __shared__ float s_hi;
    int t = threadIdx.x;
    float M = 1.f, v = 0.f;
    if (t < NB) {
        M = sqrtf(__uint_as_float(g_magmax[t]));
        v = sqrtf(__uint_as_float(g_thinmax[t])) / M;
    }
    float mx = v;
    for (int o = 16; o; o >>= 1) mx = fmaxf(mx, __shfl_xor_sync(0xffffffffu, mx, o));
    if (t == 0) s_hi = mx * 0.15f;
    __syncwarp();
    float hiv = s_hi;
    if (t < NB) {
        unsigned lo, hi_, mid;
        lo = 0u; hi_ = 0x7F800000u;
        while (lo < hi_) {
            mid = (lo + hi_) >> 1;
            if (sqrtf(__uint_as_float(mid)) / M >= hiv) hi_ = mid; else lo = mid + 1u;
        }
        float thrH = __uint_as_float(lo);
        lo = 0u; hi_ = 0x7F800000u;
        while (lo < hi_) {
            mid = (lo + hi_) >> 1;
            if (sqrtf(__uint_as_float(mid)) / M >= 0.00392f) hi_ = mid; else lo = mid + 1u;
        }
        g_thr[t] = make_float2(thrH, __uint_as_float(lo));
    }
}

// ---------------------------------------------------------------- hysteresis pass on bitmaps
// Tile = 128 rows x full 1024-px width, 512 threads. Pass 0 fuses classification
// (reads g_thin, builds bitmaps in-tile via ballots, writes both bitmaps
// unconditionally for replay determinism). Word-parallel 8-neighbor dilation to
// tile-local fixpoint; halos from neighbor tiles' previous-pass state.
__global__ void __launch_bounds__(512) k_hystb(int pass) {
    if (pass > 0 && g_flags[pass - 1] == 0) return;   // converged: cheap no-op pass

    __shared__ unsigned us[130][WPR];
    __shared__ unsigned uw[128][WPR];
    __shared__ int s_changed, s_any;
    const int y0 = blockIdx.x * 128;
    const int b  = blockIdx.y;
    const int tid  = threadIdx.x;
    const int lane = tid & 31, wid = tid >> 5;

    if (tid == 0) s_any = 0;

    if (pass == 0) {
        const float2 thr = g_thr[b];
        const float* tp = g_thin + (size_t)b * IMG;
        for (int idx = wid; idx < 130 * WPR; idx += 16) {
            int r = idx >> 5, w = idx & 31;
            int gy = y0 + r - 1;
            float s = 0.f;
            if ((unsigned)gy < (unsigned)IH) s = tp[gy * IW + w * 32 + lane];
            bool st = (s >= thr.x);
            unsigned sv = __ballot_sync(0xffffffffu, st);
            unsigned wv = __ballot_sync(0xffffffffu, !st && (s >= thr.y));
            if (lane == 0) {
                us[r][w] = sv;
                if (r >= 1 && r <= 128) uw[r - 1][w] = wv;
            }
        }
    } else {
        const unsigned* S = g_sbits + b * WPI;
        const unsigned* W = g_wbits + b * WPI;
        for (int i = tid; i < 130 * WPR; i += 512) {
            int r = i >> 5, w = i & 31;
            int gy = y0 + r - 1;
            us[r][w] = ((unsigned)gy < (unsigned)IH) ? S[gy * WPR + w] : 0u;
        }
        for (int i = tid; i < 128 * WPR; i += 512) {
            int r = i >> 5, w = i & 31;
            uw[r][w] = W[(y0 + r) * WPR + w];
        }
    }

    for (;;) {
        __syncthreads();
        if (tid == 0) s_changed = 0;
        __syncthreads();
        for (int p = tid; p < 128 * WPR; p += 512) {
            int r = p >> 5, w = p & 31;
            unsigned wk = uw[r][w];
            if (!wk) continue;
            unsigned cen = us[r + 1][w];
            wk &= ~cen;
            if (!wk) continue;
            unsigned up = us[r][w], dn = us[r + 2][w];
            unsigned pu = w ? us[r][w - 1] : 0u,      nu = (w < 31) ? us[r][w + 1] : 0u;
            unsigned pc = w ? us[r + 1][w - 1] : 0u,  nc = (w < 31) ? us[r + 1][w + 1] : 0u;
            unsigned pd = w ? us[r + 2][w - 1] : 0u,  nd = (w < 31) ? us[r + 2][w + 1] : 0u;
            unsigned nb = up | (up << 1) | (up >> 1) | (pu >> 31) | (nu << 31)
                        | dn | (dn << 1) | (dn >> 1) | (pd >> 31) | (nd << 31)
                        |      (cen << 1) | (cen >> 1) | (pc >> 31) | (nc << 31);
            unsigned ns = wk & nb;
            if (ns) { us[r + 1][w] = cen | ns; s_changed = 1; s_any = 1; }
        }
        __syncthreads();
        if (!s_changed) break;
    }

    unsigned* So = g_sbits + b * WPI;
    if (pass == 0) {
        unsigned* Wo = g_wbits + b * WPI;
        for (int i = tid; i < 128 * WPR; i += 512) {
            int r = i >> 5, w = i & 31;
            So[(y0 + r) * WPR + w] = us[r + 1][w];
            Wo[(y0 + r) * WPR + w] = uw[r][w];
        }
        if (tid == 0 && s_any) g_flags[0] = 1;
    } else if (s_any) {
        for (int i = tid; i < 128 * WPR; i += 512) {
            int r = i >> 5, w = i & 31;
            So[(y0 + r) * WPR + w] = us[r + 1][w];
        }
        if (tid == 0) g_flags[pass] = 1;
    }
}

// ---------------------------------------------------------------- final write (4 px/thread, float4)
__global__ void __launch_bounds__(256) k_final(float4* __restrict__ out) {
    int q = blockIdx.x * 256 + threadIdx.x;     // quad index
    int i = q * 4;
    unsigned w = g_sbits[i >> 5];
    unsigned sh = (w >> (i & 31));
    float4 v;
    v.x = (sh & 1u) ? 255.0f : 0.0f;
    v.y = (sh & 2u) ? 255.0f : 0.0f;
    v.z = (sh & 4u) ? 255.0f : 0.0f;
    v.w = (sh & 8u) ? 255.0f : 0.0f;
    out[q] = v;
}

// ---------------------------------------------------------------- launch
extern "C" void kernel_launch(void* const* d_in, const int* in_sizes, int n_in,
                              void* d_out, int out_size) {
    (void)in_sizes; (void)n_in; (void)out_size;
    const float* img = (const float*)d_in[0];

    dim3 tg(32, 16, 16);       // 32-wide x 64-tall tiles
    dim3 hg(8, 16);            // 128-row stripes x 16 batches

    k_reset<<<1, 64>>>();
    k_main<<<tg, 256>>>(img);
    k_hi<<<1, 32>>>();
    for (int p = 0; p < NPASS; p++) k_hystb<<<hg, 512>>>(p);
    k_final<<<TOTAL / 1024, 256>>>((float4*)d_out);
}

// round 13
// speedup vs baseline: 1.4069x; 1.4069x over previous
#include <cuda_runtime.h>
#include <math.h>

// Problem constants
static constexpr int IW = 1024;
static constexpr int IH = 1024;
static constexpr int NB = 16;
static constexpr int IMG = IW * IH;           // 1<<20
static constexpr int TOTAL = NB * IMG;        // 16M
static constexpr int NPASS = 12;
static constexpr int WPR = IW / 32;           // 32 words per row
static constexpr int WPI = IMG / 32;          // words per image

// Scratch (device globals: allocation-free rule)
__device__ float         g_thin[TOTAL];        // 64MB SQUARED thin magnitudes
__device__ unsigned int  g_sbits[TOTAL / 32];  // 2MB strong bitmap
__device__ unsigned int  g_wbits[TOTAL / 32];  // 2MB weak bitmap
__device__ unsigned int  g_magmax[NB];         // per-batch max squared mag, float bits
__device__ unsigned int  g_thinmax[NB];        // per-batch max squared thin, float bits
__device__ float2        g_thr[NB];            // per-batch squared-domain thresholds (hi, lo)
__device__ int           g_flags[NPASS];       // hysteresis per-pass "changed" flags

// ---------------------------------------------------------------- reset
__global__ void k_reset() {
    int t = threadIdx.x;
    if (t < NB) { g_magmax[t] = 0u; g_thinmax[t] = 0u; }
    if (t < NPASS) g_flags[t] = 0;
}

// ---------------------------------------------------------------- fused blur + sobel + NMS (squared domain)
// Tile: 64 rows x 32 cols per block, 256 threads.
__global__ void __launch_bounds__(256) k_main(const float* __restrict__ img) {
    __shared__ float         si[72][40];   // raw img, halo 4
    __shared__ float         hb[72][36];   // horizontal blur
    __shared__ float         sb[68][36];   // blurred, halo 2 (0 outside image = conv padding)
    __shared__ float         sm[66][34];   // SQUARED mag, halo 1 (0 outside image)
    __shared__ unsigned char sd[66][34];   // NMS axis code
    __shared__ float red[16];
    const int b  = blockIdx.z;
    const int x0 = blockIdx.x * 32, y0 = blockIdx.y * 64;
    const float* im = img + (size_t)b * IMG;
    const int tid = threadIdx.x;

    const bool interior = (x0 >= 4) && (x0 + 36 <= IW) && (y0 >= 4) && (y0 + 68 <= IH);
    if (interior) {
        const float* base = im + (y0 - 4) * IW + (x0 - 4);
        for (int i = tid; i < 72 * 40; i += 256) {
            int r = i / 40, c = i % 40;
            si[r][c] = base[r * IW + c];
        }
    } else {
        for (int i = tid; i < 72 * 40; i += 256) {
            int r = i / 40, c = i % 40;
            int gy = y0 + r - 4, gx = x0 + c - 4;
            float v = 0.f;
            if ((unsigned)gy < (unsigned)IH && (unsigned)gx < (unsigned)IW) v = im[gy * IW + gx];
            si[r][c] = v;
        }
    }
    __syncthreads();

    // unnormalized gaussian window, sigma=1, K=5
    const float G0 = 0.13533528323661270231f;  // exp(-2)
    const float G1 = 0.60653065971263342360f;  // exp(-0.5)

    for (int i = tid; i < 72 * 36; i += 256) {
        int r = i / 36, c = i % 36;
        float v = G0 * si[r][c];
        v += G1 * si[r][c + 1];
        v += si[r][c + 2];
        v += G1 * si[r][c + 3];
        v += G0 * si[r][c + 4];
        hb[r][c] = v;
    }
    __syncthreads();

    for (int i = tid; i < 68 * 36; i += 256) {
        int r = i / 36, c = i % 36;
        int gy = y0 + r - 2, gx = x0 + c - 2;
        float v = 0.f;
        if ((unsigned)gy < (unsigned)IH && (unsigned)gx < (unsigned)IW) {
            v = G0 * hb[r][c];
            v += G1 * hb[r + 1][c];
            v += hb[r + 2][c];
            v += G1 * hb[r + 3][c];
            v += G0 * hb[r + 4][c];
        }
        sb[r][c] = v;
    }
    __syncthreads();

    const float T1 = 0.41421356237309503f;   // tan(22.5 deg)
    for (int i = tid; i < 66 * 34; i += 256) {
        int r = i / 34, c = i % 34;
        int gy = y0 + r - 1, gx = x0 + c - 1;
        float m = 0.f;
        unsigned char code = 0;
        if ((unsigned)gy < (unsigned)IH && (unsigned)gx < (unsigned)IW) {
            float a0 = sb[r][c],     a1 = sb[r][c + 1],     a2 = sb[r][c + 2];
            float b0 = sb[r + 1][c],                        b2 = sb[r + 1][c + 2];
            float c0 = sb[r + 2][c], c1 = sb[r + 2][c + 1], c2 = sb[r + 2][c + 2];
            float Ix = (a0 - a2) + 2.f * (b0 - b2) + (c0 - c2);
            float Iy = (a0 - c0) + 2.f * (a1 - c1) + (a2 - c2);
            m = Ix * Ix + Iy * Iy;     // squared magnitude (no sqrt)
            // Quantized NMS axis (only idx mod 4 matters; ties match round-half-even)
            float ax = fabsf(Ix), ay = fabsf(Iy);
            if (ay <= T1 * ax)      code = 0;                                   // E-W
            else if (ax <= T1 * ay) code = 1;                                   // N-S
            else if ((__float_as_int(Ix) ^ __float_as_int(Iy)) >= 0) code = 2;  // 45 deg
            else                    code = 3;                                   // 135 deg
        }
        sm[r][c] = m;
        sd[r][c] = code;
    }
    __syncthreads();

    const int cx = tid & 31;
    const int r0 = tid >> 5;
    float mmax = 0.f, tmax = 0.f;
    float* tp = g_thin + (size_t)b * IMG;

#pragma unroll
    for (int k = 0; k < 8; k++) {
        const int ry = r0 + 8 * k;
        const int r = ry + 1, c = cx + 1;
        float m = sm[r][c];
        int code = sd[r][c];
        int dy = (code == 0) ? 0 : 1;
        int dx = (code == 1) ? 0 : ((code == 3) ? -1 : 1);
        float n1 = sm[r + dy][c + dx];
        float n2 = sm[r - dy][c - dx];
        float thin = (m > n1 && m > n2) ? m : 0.f;
        tp[(y0 + ry) * IW + x0 + cx] = thin;
        mmax = fmaxf(mmax, m);
        tmax = fmaxf(tmax, thin);
    }

    for (int o = 16; o; o >>= 1) {
        mmax = fmaxf(mmax, __shfl_xor_sync(0xffffffffu, mmax, o));
        tmax = fmaxf(tmax, __shfl_xor_sync(0xffffffffu, tmax, o));
    }
    int warp = tid >> 5, lane = tid & 31;
    if (lane == 0) { red[warp] = mmax; red[warp + 8] = tmax; }
    __syncthreads();
    if (tid == 0) {
        float a = red[0], t2 = red[8];
        for (int w = 1; w < 8; w++) { a = fmaxf(a, red[w]); t2 = fmaxf(t2, red[w + 8]); }
        atomicMax(&g_magmax[b], __float_as_uint(a));
        atomicMax(&g_thinmax[b], __float_as_uint(t2));
    }
}

// ---------------------------------------------------------------- thresholds (exact, squared domain)
// sqrtf is correctly rounded & monotone: max(sqrt(s_i)) == sqrt(max s_i) bit-exact.
// Binary search inverts the EXACT predicate "sqrtf(s)/M >= thr" so k_class's
// compares are boolean-identical to the reference's divide-then-compare.
__global__ void k_hi() {
    __shared__ float s_hi;
    int t = threadIdx.x;
    float M = 1.f, v = 0.f;
    if (t < NB) {
        M = sqrtf(__uint_as_float(g_magmax[t]));
        v = sqrtf(__uint_as_float(g_thinmax[t])) / M;
    }
    float mx = v;
    for (int o = 16; o; o >>= 1) mx = fmaxf(mx, __shfl_xor_sync(0xffffffffu, mx, o));
    if (t == 0) s_hi = mx * 0.15f;
    __syncwarp();
    float hiv = s_hi;
    if (t < NB) {
        unsigned lo, hi_, mid;
        lo = 0u; hi_ = 0x7F800000u;
        while (lo < hi_) {
            mid = (lo + hi_) >> 1;
            if (sqrtf(__uint_as_float(mid)) / M >= hiv) hi_ = mid; else lo = mid + 1u;
        }
        float thrH = __uint_as_float(lo);
        lo = 0u; hi_ = 0x7F800000u;
        while (lo < hi_) {
            mid = (lo + hi_) >> 1;
            if (sqrtf(__uint_as_float(mid)) / M >= 0.00392f) hi_ = mid; else lo = mid + 1u;
        }
        g_thr[t] = make_float2(thrH, __uint_as_float(lo));
    }
}

// ---------------------------------------------------------------- classify -> bitmaps (compare-only, 4 px/thread)
__global__ void __launch_bounds__(256) k_class() {
    const int warpg = blockIdx.x * 8 + (threadIdx.x >> 5);  // global warp id
    const int lane  = threadIdx.x & 31;
    const int base  = warpg * 128;                          // 128 px per warp
    const float2 thr = g_thr[base >> 20];
    unsigned sw[4], ww[4];
#pragma unroll
    for (int k = 0; k < 4; k++) {
        float s = g_thin[base + 32 * k + lane];
        bool st = (s >= thr.x);
        bool wk = !st && (s >= thr.y);
        sw[k] = __ballot_sync(0xffffffffu, st);
        ww[k] = __ballot_sync(0xffffffffu, wk);
    }
    if (lane < 4) {
        g_sbits[(base >> 5) + lane] = sw[lane];
        g_wbits[(base >> 5) + lane] = ww[lane];
    }
}

// ---------------------------------------------------------------- hysteresis pass on bitmaps
// Tile = 64 rows x full 1024-px width, 256 threads (R4 measured-good config).
__global__ void __launch_bounds__(256) k_hystb(int pass) {
    if (pass > 0 && g_flags[pass - 1] == 0) return;   // converged: cheap no-op pass

    __shared__ unsigned us[66][WPR];
    __shared__ unsigned uw[64][WPR];
    __shared__ int s_changed, s_any;
    const int y0 = blockIdx.x * 64;
    const int b  = blockIdx.y;
    const unsigned* S = g_sbits + b * WPI;
    const unsigned* W = g_wbits + b * WPI;
    const int tid = threadIdx.x;

    if (tid == 0) s_any = 0;
    for (int i = tid; i < 66 * WPR; i += 256) {
        int r = i >> 5, w = i & 31;
        int gy = y0 + r - 1;
        us[r][w] = ((unsigned)gy < (unsigned)IH) ? S[gy * WPR + w] : 0u;
    }
    for (int i = tid; i < 64 * WPR; i += 256) {
        int r = i >> 5, w = i & 31;
        uw[r][w] = W[(y0 + r) * WPR + w];
    }

    for (;;) {
        __syncthreads();
        if (tid == 0) s_changed = 0;
        __syncthreads();
        for (int p = tid; p < 64 * WPR; p += 256) {
            int r = p >> 5, w = p & 31;
            unsigned wk = uw[r][w];
            if (!wk) continue;
            unsigned cen = us[r + 1][w];
            wk &= ~cen;
            if (!wk) continue;
            unsigned up = us[r][w], dn = us[r + 2][w];
            unsigned pu = w ? us[r][w - 1] : 0u,      nu = (w < 31) ? us[r][w + 1] : 0u;
            unsigned pc = w ? us[r + 1][w - 1] : 0u,  nc = (w < 31) ? us[r + 1][w + 1] : 0u;
            unsigned pd = w ? us[r + 2][w - 1] : 0u,  nd = (w < 31) ? us[r + 2][w + 1] : 0u;
            unsigned nb = up | (up << 1) | (up >> 1) | (pu >> 31) | (nu << 31)
                        | dn | (dn << 1) | (dn >> 1) | (pd >> 31) | (nd << 31)
                        |      (cen << 1) | (cen >> 1) | (pc >> 31) | (nc << 31);
            unsigned ns = wk & nb;
            if (ns) { us[r + 1][w] = cen | ns; s_changed = 1; s_any = 1; }
        }
        __syncthreads();
        if (!s_changed) break;
    }

    if (s_any) {
        unsigned* So = g_sbits + b * WPI;
        for (int i = tid; i < 64 * WPR; i += 256) {
            int r = i >> 5, w = i & 31;
            So[(y0 + r) * WPR + w] = us[r + 1][w];
        }
        if (tid == 0) g_flags[pass] = 1;
    }
}

// ---------------------------------------------------------------- final write (4 px/thread, float4)
__global__ void __launch_bounds__(256) k_final(float4* __restrict__ out) {
    int q = blockIdx.x * 256 + threadIdx.x;     // quad index
    int i = q * 4;
    unsigned w = g_sbits[i >> 5];
    unsigned sh = (w >> (i & 31));
    float4 v;
    v.x = (sh & 1u) ? 255.0f : 0.0f;
    v.y = (sh & 2u) ? 255.0f : 0.0f;
    v.z = (sh & 4u) ? 255.0f : 0.0f;
    v.w = (sh & 8u) ? 255.0f : 0.0f;
    out[q] = v;
}

// ---------------------------------------------------------------- launch
extern "C" void kernel_launch(void* const* d_in, const int* in_sizes, int n_in,
                              void* d_out, int out_size) {
    (void)in_sizes; (void)n_in; (void)out_size;
    const float* img = (const float*)d_in[0];

    dim3 tg(32, 16, 16);       // 32-wide x 64-tall tiles
    dim3 hg(16, 16);           // 64-row stripes x 16 batches

    k_reset<<<1, 64>>>();
    k_main<<<tg, 256>>>(img);
    k_hi<<<1, 32>>>();
    k_class<<<TOTAL / (256 * 4), 256>>>();
    for (int p = 0; p < NPASS; p++) k_hystb<<<hg, 256>>>(p);
    k_final<<<TOTAL / 1024, 256>>>((float4*)d_out);
}

// round 15
// speedup vs baseline: 1.4878x; 1.0575x over previous
#include <cuda_runtime.h>
#include <math.h>

// Problem constants
static constexpr int IW = 1024;
static constexpr int IH = 1024;
static constexpr int NB = 16;
static constexpr int IMG = IW * IH;           // 1<<20
static constexpr int TOTAL = NB * IMG;        // 16M
static constexpr int WPR = IW / 32;           // 32 words per row
static constexpr int WPI = IMG / 32;          // words per image
static constexpr unsigned NBLK = 16 * 16;     // persistent hysteresis grid

// Scratch (device globals: allocation-free rule)
__device__ float         g_thin[TOTAL];        // 64MB SQUARED thin magnitudes
__device__ unsigned int  g_sbits[TOTAL / 32];  // 2MB strong bitmap
__device__ unsigned int  g_wbits[TOTAL / 32];  // 2MB weak bitmap
__device__ unsigned int  g_magmax[NB];         // per-batch max squared mag, float bits
__device__ unsigned int  g_thinmax[NB];        // per-batch max squared thin, float bits
__device__ float2        g_thr[NB];            // per-batch squared-domain thresholds (hi, lo)
__device__ unsigned int  g_bar_count;          // grid barrier arrival counter
__device__ unsigned int  g_bar_gen;            // grid barrier generation
__device__ int           g_gch[3];             // rotating global changed flags

// ---------------------------------------------------------------- reset (runs every replay)
__global__ void k_reset() {
    int t = threadIdx.x;
    if (t < NB) { g_magmax[t] = 0u; g_thinmax[t] = 0u; }
    if (t < 3)  g_gch[t] = 0;
    if (t == 0) { g_bar_count = 0u; g_bar_gen = 0u; }
}

// ---------------------------------------------------------------- fused blur + sobel + NMS (squared domain)
// Tile: 64 rows x 32 cols per block, 256 threads.
__global__ void __launch_bounds__(256) k_main(const float* __restrict__ img) {
    __shared__ float         si[72][40];   // raw img, halo 4
    __shared__ float         hb[72][36];   // horizontal blur
    __shared__ float         sb[68][36];   // blurred, halo 2 (0 outside image = conv padding)
    __shared__ float         sm[66][34];   // SQUARED mag, halo 1 (0 outside image)
    __shared__ unsigned char sd[66][34];   // NMS axis code
    __shared__ float red[16];
    const int b  = blockIdx.z;
    const int x0 = blockIdx.x * 32, y0 = blockIdx.y * 64;
    const float* im = img + (size_t)b * IMG;
    const int tid = threadIdx.x;

    const bool interior = (x0 >= 4) && (x0 + 36 <= IW) && (y0 >= 4) && (y0 + 68 <= IH);
    if (interior) {
        const float* base = im + (y0 - 4) * IW + (x0 - 4);
        for (int i = tid; i < 72 * 40; i += 256) {
            int r = i / 40, c = i % 40;
            si[r][c] = base[r * IW + c];
        }
    } else {
        for (int i = tid; i < 72 * 40; i += 256) {
            int r = i / 40, c = i % 40;
            int gy = y0 + r - 4, gx = x0 + c - 4;
            float v = 0.f;
            if ((unsigned)gy < (unsigned)IH && (unsigned)gx < (unsigned)IW) v = im[gy * IW + gx];
            si[r][c] = v;
        }
    }
    __syncthreads();

    // unnormalized gaussian window, sigma=1, K=5
    const float G0 = 0.13533528323661270231f;  // exp(-2)
    const float G1 = 0.60653065971263342360f;  // exp(-0.5)

    for (int i = tid; i < 72 * 36; i += 256) {
        int r = i / 36, c = i % 36;
        float v = G0 * si[r][c];
        v += G1 * si[r][c + 1];
        v += si[r][c + 2];
        v += G1 * si[r][c + 3];
        v += G0 * si[r][c + 4];
        hb[r][c] = v;
    }
    __syncthreads();

    for (int i = tid; i < 68 * 36; i += 256) {
        int r = i / 36, c = i % 36;
        int gy = y0 + r - 2, gx = x0 + c - 2;
        float v = 0.f;
        if ((unsigned)gy < (unsigned)IH && (unsigned)gx < (unsigned)IW) {
            v = G0 * hb[r][c];
            v += G1 * hb[r + 1][c];
            v += hb[r + 2][c];
            v += G1 * hb[r + 3][c];
            v += G0 * hb[r + 4][c];
        }
        sb[r][c] = v;
    }
    __syncthreads();

    const float T1 = 0.41421356237309503f;   // tan(22.5 deg)
    for (int i = tid; i < 66 * 34; i += 256) {
        int r = i / 34, c = i % 34;
        int gy = y0 + r - 1, gx = x0 + c - 1;
        float m = 0.f;
        unsigned char code = 0;
        if ((unsigned)gy < (unsigned)IH && (unsigned)gx < (unsigned)IW) {
            float a0 = sb[r][c],     a1 = sb[r][c + 1],     a2 = sb[r][c + 2];
            float b0 = sb[r + 1][c],                        b2 = sb[r + 1][c + 2];
            float c0 = sb[r + 2][c], c1 = sb[r + 2][c + 1], c2 = sb[r + 2][c + 2];
            float Ix = (a0 - a2) + 2.f * (b0 - b2) + (c0 - c2);
            float Iy = (a0 - c0) + 2.f * (a1 - c1) + (a2 - c2);
            m = Ix * Ix + Iy * Iy;     // squared magnitude (no sqrt)
            // Quantized NMS axis (only idx mod 4 matters; ties match round-half-even)
            float ax = fabsf(Ix), ay = fabsf(Iy);
            if (ay <= T1 * ax)      code = 0;                                   // E-W
            else if (ax <= T1 * ay) code = 1;                                   // N-S
            else if ((__float_as_int(Ix) ^ __float_as_int(Iy)) >= 0) code = 2;  // 45 deg
            else                    code = 3;                                   // 135 deg
        }
        sm[r][c] = m;
        sd[r][c] = code;
    }
    __syncthreads();

    const int cx = tid & 31;
    const int r0 = tid >> 5;
    float mmax = 0.f, tmax = 0.f;
    float* tp = g_thin + (size_t)b * IMG;

#pragma unroll
    for (int k = 0; k < 8; k++) {
        const int ry = r0 + 8 * k;
        const int r = ry + 1, c = cx + 1;
        float m = sm[r][c];
        int code = sd[r][c];
        int dy = (code == 0) ? 0 : 1;
        int dx = (code == 1) ? 0 : ((code == 3) ? -1 : 1);
        float n1 = sm[r + dy][c + dx];
        float n2 = sm[r - dy][c - dx];
        float thin = (m > n1 && m > n2) ? m : 0.f;
        tp[(y0 + ry) * IW + x0 + cx] = thin;
        mmax = fmaxf(mmax, m);
        tmax = fmaxf(tmax, thin);
    }

    for (int o = 16; o; o >>= 1) {
        mmax = fmaxf(mmax, __shfl_xor_sync(0xffffffffu, mmax, o));
        tmax = fmaxf(tmax, __shfl_xor_sync(0xffffffffu, tmax, o));
    }
    int warp = tid >> 5, lane = tid & 31;
    if (lane == 0) { red[warp] = mmax; red[warp + 8] = tmax; }
    __syncthreads();
    if (tid == 0) {
        float a = red[0], t2 = red[8];
        for (int w = 1; w < 8; w++) { a = fmaxf(a, red[w]); t2 = fmaxf(t2, red[w + 8]); }
        atomicMax(&g_magmax[b], __float_as_uint(a));
        atomicMax(&g_thinmax[b], __float_as_uint(t2));
    }
}

// ---------------------------------------------------------------- thresholds (exact, squared domain)
__global__ void k_hi() {
    __shared__ float s_hi;
    int t = threadIdx.x;
    float M = 1.f, v = 0.f;
    if (t < NB) {
        M = sqrtf(__uint_as_float(g_magmax[t]));
        v = sqrtf(__uint_as_float(g_thinmax[t])) / M;
    }
    float mx = v;
    for (int o = 16; o; o >>= 1) mx = fmaxf(mx, __shfl_xor_sync(0xffffffffu, mx, o));
    if (t == 0) s_hi = mx * 0.15f;
    __syncwarp();
    float hiv = s_hi;
    if (t < NB) {
        unsigned lo, hi_, mid;
        lo = 0u; hi_ = 0x7F800000u;
        while (lo < hi_) {
            mid = (lo + hi_) >> 1;
            if (sqrtf(__uint_as_float(mid)) / M >= hiv) hi_ = mid; else lo = mid + 1u;
        }
        float thrH = __uint_as_float(lo);
        lo = 0u; hi_ = 0x7F800000u;
        while (lo < hi_) {
            mid = (lo + hi_) >> 1;
            if (sqrtf(__uint_as_float(mid)) / M >= 0.00392f) hi_ = mid; else lo = mid + 1u;
        }
        g_thr[t] = make_float2(thrH, __uint_as_float(lo));
    }
}

// ---------------------------------------------------------------- classify -> bitmaps (compare-only, 4 px/thread)
__global__ void __launch_bounds__(256) k_class() {
    const int warpg = blockIdx.x * 8 + (threadIdx.x >> 5);  // global warp id
    const int lane  = threadIdx.x & 31;
    const int base  = warpg * 128;                          // 128 px per warp
    const float2 thr = g_thr[base >> 20];
    unsigned sw[4], ww[4];
#pragma unroll
    for (int k = 0; k < 4; k++) {
        float s = g_thin[base + 32 * k + lane];
        bool st = (s >= thr.x);
        bool wk = !st && (s >= thr.y);
        sw[k] = __ballot_sync(0xffffffffu, st);
        ww[k] = __ballot_sync(0xffffffffu, wk);
    }
    if (lane < 4) {
        g_sbits[(base >> 5) + lane] = sw[lane];
        g_wbits[(base >> 5) + lane] = ww[lane];
    }
}

// ---------------------------------------------------------------- persistent hysteresis + final output
// 256 blocks (16 stripes x 16 batches), all co-resident -> software grid sync is safe.
// Each global iteration: tile-local fixpoint in smem, write-back if changed,
// grid barrier, uniform converged check, reload 2 halo rows. On convergence the
// block's smem rows equal global state, so output is written directly from smem.
__global__ void __launch_bounds__(256) k_hyst_p(float4* __restrict__ out) {
    __shared__ unsigned us[66][WPR];
    __shared__ unsigned uw[64][WPR];
    __shared__ int s_changed;
    __shared__ int s_gch;
    const int y0 = blockIdx.x * 64;
    const int b  = blockIdx.y;
    unsigned* S = g_sbits + b * WPI;
    const unsigned* W = g_wbits + b * WPI;
    const int tid = threadIdx.x;
    const bool isMaster = (blockIdx.x == 0 && blockIdx.y == 0);

    for (int i = tid; i < 66 * WPR; i += 256) {
        int r = i >> 5, w = i & 31;
        int gy = y0 + r - 1;
        us[r][w] = ((unsigned)gy < (unsigned)IH) ? S[gy * WPR + w] : 0u;
    }
    for (int i = tid; i < 64 * WPR; i += 256) {
        int r = i >> 5, w = i & 31;
        uw[r][w] = W[(y0 + r) * WPR + w];
    }

    for (int it = 0; ; ++it) {
        // ---- tile-local fixpoint ----
        int blockChanged = 0;
        for (;;) {
            __syncthreads();
            if (tid == 0) s_changed = 0;
            __syncthreads();
            for (int p = tid; p < 64 * WPR; p += 256) {
                int r = p >> 5, w = p & 31;
                unsigned wk = uw[r][w];
                if (!wk) continue;
                unsigned cen = us[r + 1][w];
                wk &= ~cen;
                if (!wk) continue;
                unsigned up = us[r][w], dn = us[r + 2][w];
                unsigned pu = w ? us[r][w - 1] : 0u,      nu = (w < 31) ? us[r][w + 1] : 0u;
                unsigned pc = w ? us[r + 1][w - 1] : 0u,  nc = (w < 31) ? us[r + 1][w + 1] : 0u;
                unsigned pd = w ? us[r + 2][w - 1] : 0u,  nd = (w < 31) ? us[r + 2][w + 1] : 0u;
                unsigned nb = up | (up << 1) | (up >> 1) | (pu >> 31) | (nu << 31)
                            | dn | (dn << 1) | (dn >> 1) | (pd >> 31) | (nd << 31)
                            |      (cen << 1) | (cen >> 1) | (pc >> 31) | (nc << 31);
                unsigned ns = wk & nb;
                if (ns) { us[r + 1][w] = cen | ns; s_changed = 1; }
            }
            __syncthreads();
            if (!s_changed) break;
            blockChanged = 1;
        }

        // ---- write back + raise global flag ----
        if (blockChanged) {
            for (int i = tid; i < 64 * WPR; i += 256) {
                int r = i >> 5, w = i & 31;
                S[(y0 + r) * WPR + w] = us[r + 1][w];
            }
            if (tid == 0) atomicExch(&g_gch[it % 3], 1);
        }

        // ---- grid barrier + uniform converged check ----
        __syncthreads();                       // all smem/global writes of this block done
        if (tid == 0) {
            __threadfence();                   // publish S writes + flag before arrival
            unsigned gen = atomicAdd(&g_bar_gen, 0u);   // read BEFORE arrival
            if (atomicAdd(&g_bar_count, 1u) == NBLK - 1u) {
                atomicExch(&g_bar_count, 0u);
                __threadfence();
                atomicAdd(&g_bar_gen, 1u);     // release
            } else {
                while (atomicAdd(&g_bar_gen, 0u) == gen) __nanosleep(64);
            }
            __threadfence();
            s_gch = atomicAdd(&g_gch[it % 3], 0);
            // reset slot for iteration it+2: no block can write it until after
            // barrier(it+1), which cannot release before we arrive there.
            if (isMaster) atomicExch(&g_gch[(it + 2) % 3], 0);
        }
        __syncthreads();
        if (!s_gch) break;

        // ---- reload halo rows (neighbor stripes may have changed) ----
        if (tid < 2 * WPR) {
            int r = (tid >> 5) ? 65 : 0;
            int w = tid & 31;
            int gy = y0 + r - 1;
            us[r][w] = ((unsigned)gy < (unsigned)IH) ? S[gy * WPR + w] : 0u;
        }
        // fixpoint loop's leading __syncthreads orders this load
    }

    // ---- converged: write final output directly from smem ----
    float4* op = out + ((size_t)b * IMG + (size_t)y0 * IW) / 4;
    for (int i = tid; i < 64 * 256; i += 256) {
        int r = i >> 8, q = i & 255;
        unsigned bits = us[r + 1][q >> 3] >> ((q & 7) * 4);
        float4 v;
        v.x = (bits & 1u) ? 255.0f : 0.0f;
        v.y = (bits & 2u) ? 255.0f : 0.0f;
        v.z = (bits & 4u) ? 255.0f : 0.0f;
        v.w = (bits & 8u) ? 255.0f : 0.0f;
        op[r * (IW / 4) + q] = v;
    }
}

// ---------------------------------------------------------------- launch
extern "C" void kernel_launch(void* const* d_in, const int* in_sizes, int n_in,
                              void* d_out, int out_size) {
    (void)in_sizes; (void)n_in; (void)out_size;
    const float* img = (const float*)d_in[0];

    dim3 tg(32, 16, 16);       // 32-wide x 64-tall tiles
    dim3 hg(16, 16);           // 64-row stripes x 16 batches (all co-resident)

    k_reset<<<1, 64>>>();
    k_main<<<tg, 256>>>(img);
    k_hi<<<1, 32>>>();
    k_class<<<TOTAL / (256 * 4), 256>>>();
    k_hyst_p<<<hg, 256>>>((float4*)d_out);
}

// round 17
// speedup vs baseline: 1.6756x; 1.1262x over previous
#include <cuda_runtime.h>
#include <math.h>

// Problem constants
static constexpr int IW = 1024;
static constexpr int IH = 1024;
static constexpr int NB = 16;
static constexpr int IMG = IW * IH;           // 1<<20
static constexpr int TOTAL = NB * IMG;        // 16M
static constexpr int WPR = IW / 32;           // 32 words per row
static constexpr int WPI = IMG / 32;          // words per image
static constexpr unsigned NBLK = 16 * 16;     // persistent hysteresis grid

// Scratch (device globals: allocation-free rule)
__device__ float         g_thin[TOTAL];        // 64MB SQUARED thin magnitudes
__device__ unsigned int  g_sbits[TOTAL / 32];  // 2MB strong bitmap
__device__ unsigned int  g_wbits[TOTAL / 32];  // 2MB weak bitmap
__device__ unsigned int  g_magmax[NB];         // per-batch max squared mag, float bits
__device__ unsigned int  g_thinmax[NB];        // per-batch max squared thin, float bits
__device__ float2        g_thr[NB];            // per-batch squared-domain thresholds (hi, lo)
__device__ unsigned int  g_bar_count;          // grid barrier arrival counter
__device__ unsigned int  g_bar_gen;            // grid barrier generation
__device__ int           g_gch[3];             // rotating global changed flags

// ---------------------------------------------------------------- reset (runs every replay)
__global__ void k_reset() {
    int t = threadIdx.x;
    if (t < NB) { g_magmax[t] = 0u; g_thinmax[t] = 0u; }
    if (t < 3)  g_gch[t] = 0;
    if (t == 0) { g_bar_count = 0u; g_bar_gen = 0u; }
}

// no-op spacers: put k_main at launch index 3 so ncu profiles it
__global__ void k_nop() {}

// ---------------------------------------------------------------- fused blur + sobel + NMS (squared domain)
// Tile: 64 rows x 32 cols per block, 256 threads. All stage loops use
// shift/mask indexing (main 32-col region + small halo-column loops).
__global__ void __launch_bounds__(256) k_main(const float* __restrict__ img) {
    __shared__ float         si[72][48];   // raw img, gx = x0-8+c (float4-loadable)
    __shared__ float         hb[72][36];   // horizontal blur, gx = x0-2+c
    __shared__ float         sb[68][36];   // blurred, halo 2 (0 outside image = conv padding)
    __shared__ float         sm[66][34];   // SQUARED mag, halo 1 (0 outside image)
    __shared__ unsigned char sd[66][34];   // NMS axis code
    __shared__ float red[16];
    const int b  = blockIdx.z;
    const int x0 = blockIdx.x * 32, y0 = blockIdx.y * 64;
    const float* im = img + (size_t)b * IMG;
    const int tid = threadIdx.x;
    const int cx = tid & 31;
    const int r8 = tid >> 5;

    const bool interior = (x0 >= 8) && (x0 + 40 <= IW) && (y0 >= 4) && (y0 + 68 <= IH);
    if (interior) {
        // 12 float4 per row, base aligned (x0-8 is a multiple of 8 floats = 32B)
        const float4* base = (const float4*)(im + (y0 - 4) * IW + (x0 - 8));
        for (int i = tid; i < 72 * 12; i += 256) {
            int r = i / 12, c4 = i % 12;
            ((float4*)si[r])[c4] = base[r * (IW / 4) + c4];
        }
    } else {
        for (int i = tid; i < 72 * 48; i += 256) {
            int r = i / 48, c = i % 48;    // NOTE: 48 not a power of 2 -- must be %, not &
            int gy = y0 + r - 4, gx = x0 + c - 8;
            float v = 0.f;
            if ((unsigned)gy < (unsigned)IH && (unsigned)gx < (unsigned)IW) v = im[gy * IW + gx];
            si[r][c] = v;
        }
    }
    __syncthreads();

    // unnormalized gaussian window, sigma=1, K=5
    const float G0 = 0.13533528323661270231f;  // exp(-2)
    const float G1 = 0.60653065971263342360f;  // exp(-0.5)

    // hblur: 72 rows x 36 cols. hb[r][c] at gx = x0+c-2 reads si cols c+4..c+8.
#pragma unroll
    for (int r = r8; r < 72; r += 8) {
        float v = G0 * si[r][cx + 4];
        v += G1 * si[r][cx + 5];
        v += si[r][cx + 6];
        v += G1 * si[r][cx + 7];
        v += G0 * si[r][cx + 8];
        hb[r][cx] = v;
    }
    for (int i = tid; i < 72 * 4; i += 256) {   // halo cols 32..35
        int r = i >> 2, c = 32 + (i & 3);
        float v = G0 * si[r][c + 4];
        v += G1 * si[r][c + 5];
        v += si[r][c + 6];
        v += G1 * si[r][c + 7];
        v += G0 * si[r][c + 8];
        hb[r][c] = v;
    }
    __syncthreads();

    // vblur: 68 rows x 36 cols, zero outside image (conv zero-padding)
#pragma unroll
    for (int r = r8; r < 68; r += 8) {
        int gy = y0 + r - 2, gx = x0 + cx - 2;
        float v = 0.f;
        if ((unsigned)gy < (unsigned)IH && (unsigned)gx < (unsigned)IW) {
            v = G0 * hb[r][cx];
            v += G1 * hb[r + 1][cx];
            v += hb[r + 2][cx];
            v += G1 * hb[r + 3][cx];
            v += G0 * hb[r + 4][cx];
        }
        sb[r][cx] = v;
    }
    for (int i = tid; i < 68 * 4; i += 256) {   // halo cols 32..35
        int r = i >> 2, c = 32 + (i & 3);
        int gy = y0 + r - 2, gx = x0 + c - 2;
        float v = 0.f;
        if ((unsigned)gy < (unsigned)IH && (unsigned)gx < (unsigned)IW) {
            v = G0 * hb[r][c];
            v += G1 * hb[r + 1][c];
            v += hb[r + 2][c];
            v += G1 * hb[r + 3][c];
            v += G0 * hb[r + 4][c];
        }
        sb[r][c] = v;
    }
    __syncthreads();

    // mag + axis code: 66 rows x 34 cols
    const float T1 = 0.41421356237309503f;   // tan(22.5 deg)
#pragma unroll 1
    for (int r = r8; r < 66; r += 8) {
        int gy = y0 + r - 1, gx = x0 + cx - 1;
        float m = 0.f;
        unsigned char code = 0;
        if ((unsigned)gy < (unsigned)IH && (unsigned)gx < (unsigned)IW) {
            float a0 = sb[r][cx],     a1 = sb[r][cx + 1],     a2 = sb[r][cx + 2];
            float b0 = sb[r + 1][cx],                         b2 = sb[r + 1][cx + 2];
            float c0 = sb[r + 2][cx], c1 = sb[r + 2][cx + 1], c2 = sb[r + 2][cx + 2];
            float Ix = (a0 - a2) + 2.f * (b0 - b2) + (c0 - c2);
            float Iy = (a0 - c0) + 2.f * (a1 - c1) + (a2 - c2);
            m = Ix * Ix + Iy * Iy;     // squared magnitude (no sqrt)
            float ax = fabsf(Ix), ay = fabsf(Iy);
            if (ay <= T1 * ax)      code = 0;                                   // E-W
            else if (ax <= T1 * ay) code = 1;                                   // N-S
            else if ((__float_as_int(Ix) ^ __float_as_int(Iy)) >= 0) code = 2;  // 45 deg
            else                    code = 3;                                   // 135 deg
        }
        sm[r][cx] = m;
        sd[r][cx] = code;
    }
    for (int i = tid; i < 66 * 2; i += 256) {   // halo cols 32, 33
        int r = i >> 1, c = 32 + (i & 1);
        int gy = y0 + r - 1, gx = x0 + c - 1;
        float m = 0.f;
        unsigned char code = 0;
        if ((unsigned)gy < (unsigned)IH && (unsigned)gx < (unsigned)IW) {
            float a0 = sb[r][c],     a1 = sb[r][c + 1],     a2 = sb[r][c + 2];
            float b0 = sb[r + 1][c],                        b2 = sb[r + 1][c + 2];
            float c0 = sb[r + 2][c], c1 = sb[r + 2][c + 1], c2 = sb[r + 2][c + 2];
            float Ix = (a0 - a2) + 2.f * (b0 - b2) + (c0 - c2);
            float Iy = (a0 - c0) + 2.f * (a1 - c1) + (a2 - c2);
            m = Ix * Ix + Iy * Iy;
            float ax = fabsf(Ix), ay = fabsf(Iy);
            if (ay <= T1 * ax)      code = 0;
            else if (ax <= T1 * ay) code = 1;
            else if ((__float_as_int(Ix) ^ __float_as_int(Iy)) >= 0) code = 2;
            else                    code = 3;
        }
        sm[r][c] = m;
        sd[r][c] = code;
    }
    __syncthreads();

    // NMS: 64 rows x 32 cols
    float mmax = 0.f, tmax = 0.f;
    float* tp = g_thin + (size_t)b * IMG;
#pragma unroll
    for (int k = 0; k < 8; k++) {
        const int ry = r8 + 8 * k;
        const int r = ry + 1, c = cx + 1;
        float m = sm[r][c];
        int code = sd[r][c];
        int dy = (code == 0) ? 0 : 1;
        int dx = (code == 1) ? 0 : ((code == 3) ? -1 : 1);
        float n1 = sm[r + dy][c + dx];
        float n2 = sm[r - dy][c - dx];
        float thin = (m > n1 && m > n2) ? m : 0.f;
        tp[(y0 + ry) * IW + x0 + cx] = thin;
        mmax = fmaxf(mmax, m);
        tmax = fmaxf(tmax, thin);
    }

    for (int o = 16; o; o >>= 1) {
        mmax = fmaxf(mmax, __shfl_xor_sync(0xffffffffu, mmax, o));
        tmax = fmaxf(tmax, __shfl_xor_sync(0xffffffffu, tmax, o));
    }
    int warp = tid >> 5, lane = tid & 31;
    if (lane == 0) { red[warp] = mmax; red[warp + 8] = tmax; }
    __syncthreads();
    if (tid == 0) {
        float a = red[0], t2 = red[8];
        for (int w = 1; w < 8; w++) { a = fmaxf(a, red[w]); t2 = fmaxf(t2, red[w + 8]); }
        atomicMax(&g_magmax[b], __float_as_uint(a));
        atomicMax(&g_thinmax[b], __float_as_uint(t2));
    }
}

// ---------------------------------------------------------------- thresholds (exact, squared domain)
__global__ void k_hi() {
    __shared__ float s_hi;
    int t = threadIdx.x;
    float M = 1.f, v = 0.f;
    if (t < NB) {
        M = sqrtf(__uint_as_float(g_magmax[t]));
        v = sqrtf(__uint_as_float(g_thinmax[t])) / M;
    }
    float mx = v;
    for (int o = 16; o; o >>= 1) mx = fmaxf(mx, __shfl_xor_sync(0xffffffffu, mx, o));
    if (t == 0) s_hi = mx * 0.15f;
    __syncwarp();
    float hiv = s_hi;
    if (t < NB) {
        unsigned lo, hi_, mid;
        lo = 0u; hi_ = 0x7F800000u;
        while (lo < hi_) {
            mid = (lo + hi_) >> 1;
            if (sqrtf(__uint_as_float(mid)) / M >= hiv) hi_ = mid; else lo = mid + 1u;
        }
        float thrH = __uint_as_float(lo);
        lo = 0u; hi_ = 0x7F800000u;
        while (lo < hi_) {
            mid = (lo + hi_) >> 1;
            if (sqrtf(__uint_as_float(mid)) / M >= 0.00392f) hi_ = mid; else lo = mid + 1u;
        }
        g_thr[t] = make_float2(thrH, __uint_as_float(lo));
    }
}

// ---------------------------------------------------------------- classify -> bitmaps (float4 + nibble shuffle)
__global__ void __launch_bounds__(256) k_class() {
    const int q    = blockIdx.x * 256 + threadIdx.x;   // quad index (4 px)
    const int lane = threadIdx.x & 31;
    const float2 thr = g_thr[q >> 18];                 // (q*4) >> 20
    float4 s = ((const float4*)g_thin)[q];
    unsigned sn = 0, wn = 0;
    {
        bool s0 = s.x >= thr.x, s1 = s.y >= thr.x, s2 = s.z >= thr.x, s3 = s.w >= thr.x;
        bool w0 = !s0 && s.x >= thr.y, w1 = !s1 && s.y >= thr.y;
        bool w2 = !s2 && s.z >= thr.y, w3 = !s3 && s.w >= thr.y;
        sn = (unsigned)s0 | ((unsigned)s1 << 1) | ((unsigned)s2 << 2) | ((unsigned)s3 << 3);
        wn = (unsigned)w0 | ((unsigned)w1 << 1) | ((unsigned)w2 << 2) | ((unsigned)w3 << 3);
    }
    const int sh = 4 * (lane & 7);
    unsigned sv = sn << sh, wv = wn << sh;
    sv |= __shfl_xor_sync(0xffffffffu, sv, 1);
    wv |= __shfl_xor_sync(0xffffffffu, wv, 1);
    sv |= __shfl_xor_sync(0xffffffffu, sv, 2);
    wv |= __shfl_xor_sync(0xffffffffu, wv, 2);
    sv |= __shfl_xor_sync(0xffffffffu, sv, 4);
    wv |= __shfl_xor_sync(0xffffffffu, wv, 4);
    if ((lane & 7) == 0) {
        g_sbits[q >> 3] = sv;
        g_wbits[q >> 3] = wv;
    }
}

// ---------------------------------------------------------------- persistent hysteresis + final output
__global__ void __launch_bounds__(256) k_hyst_p(float4* __restrict__ out) {
    __shared__ unsigned us[66][WPR];
    __shared__ unsigned uw[64][WPR];
    __shared__ int s_changed;
    __shared__ int s_gch;
    const int y0 = blockIdx.x * 64;
    const int b  = blockIdx.y;
    unsigned* S = g_sbits + b * WPI;
    const unsigned* W = g_wbits + b * WPI;
    const int tid = threadIdx.x;
    const bool isMaster = (blockIdx.x == 0 && blockIdx.y == 0);

    for (int i = tid; i < 66 * WPR; i += 256) {
        int r = i >> 5, w = i & 31;
        int gy = y0 + r - 1;
        us[r][w] = ((unsigned)gy < (unsigned)IH) ? S[gy * WPR + w] : 0u;
    }
    for (int i = tid; i < 64 * WPR; i += 256) {
        int r = i >> 5, w = i & 31;
        uw[r][w] = W[(y0 + r) * WPR + w];
    }

    for (int it = 0; ; ++it) {
        // ---- tile-local fixpoint ----
        int blockChanged = 0;
        for (;;) {
            __syncthreads();
            if (tid == 0) s_changed = 0;
            __syncthreads();
            for (int p = tid; p < 64 * WPR; p += 256) {
                int r = p >> 5, w = p & 31;
                unsigned wk = uw[r][w];
                if (!wk) continue;
                unsigned cen = us[r + 1][w];
                wk &= ~cen;
                if (!wk) continue;
                unsigned up = us[r][w], dn = us[r + 2][w];
                unsigned pu = w ? us[r][w - 1] : 0u,      nu = (w < 31) ? us[r][w + 1] : 0u;
                unsigned pc = w ? us[r + 1][w - 1] : 0u,  nc = (w < 31) ? us[r + 1][w + 1] : 0u;
                unsigned pd = w ? us[r + 2][w - 1] : 0u,  nd = (w < 31) ? us[r + 2][w + 1] : 0u;
                unsigned nb = up | (up << 1) | (up >> 1) | (pu >> 31) | (nu << 31)
                            | dn | (dn << 1) | (dn >> 1) | (pd >> 31) | (nd << 31)
                            |      (cen << 1) | (cen >> 1) | (pc >> 31) | (nc << 31);
                unsigned ns = wk & nb;
                if (ns) { us[r + 1][w] = cen | ns; s_changed = 1; }
            }
            __syncthreads();
            if (!s_changed) break;
            blockChanged = 1;
        }

        // ---- write back + raise global flag ----
        if (blockChanged) {
            for (int i = tid; i < 64 * WPR; i += 256) {
                int r = i >> 5, w = i & 31;
                S[(y0 + r) * WPR + w] = us[r + 1][w];
            }
            if (tid == 0) atomicExch(&g_gch[it % 3], 1);
        }

        // ---- grid barrier + uniform converged check ----
        __syncthreads();
        if (tid == 0) {
            __threadfence();
            unsigned gen = atomicAdd(&g_bar_gen, 0u);
            if (atomicAdd(&g_bar_count, 1u) == NBLK - 1u) {
                atomicExch(&g_bar_count, 0u);
                __threadfence();
                atomicAdd(&g_bar_gen, 1u);
            } else {
                while (atomicAdd(&g_bar_gen, 0u) == gen) __nanosleep(64);
            }
            __threadfence();
            s_gch = atomicAdd(&g_gch[it % 3], 0);
            if (isMaster) atomicExch(&g_gch[(it + 2) % 3], 0);
        }
        __syncthreads();
        if (!s_gch) break;

        // ---- reload halo rows ----
        if (tid < 2 * WPR) {
            int r = (tid >> 5) ? 65 : 0;
            int w = tid & 31;
            int gy = y0 + r - 1;
            us[r][w] = ((unsigned)gy < (unsigned)IH) ? S[gy * WPR + w] : 0u;
        }
    }

    // ---- converged: write final output directly from smem ----
    float4* op = out + ((size_t)b * IMG + (size_t)y0 * IW) / 4;
    for (int i = tid; i < 64 * 256; i += 256) {
        int r = i >> 8, q = i & 255;
        unsigned bits = us[r + 1][q >> 3] >> ((q & 7) * 4);
        float4 v;
        v.x = (bits & 1u) ? 255.0f : 0.0f;
        v.y = (bits & 2u) ? 255.0f : 0.0f;
        v.z = (bits & 4u) ? 255.0f : 0.0f;
        v.w = (bits & 8u) ? 255.0f : 0.0f;
        op[r * (IW / 4) + q] = v;
    }
}

// ---------------------------------------------------------------- launch
extern "C" void kernel_launch(void* const* d_in, const int* in_sizes, int n_in,
                              void* d_out, int out_size) {
    (void)in_sizes; (void)n_in; (void)out_size;
    const float* img = (const float*)d_in[0];

    dim3 tg(32, 16, 16);       // 32-wide x 64-tall tiles
    dim3 hg(16, 16);           // 64-row stripes x 16 batches (all co-resident)

    k_reset<<<1, 64>>>();
    k_nop<<<1, 32>>>();        // spacers: k_main lands at launch index 3 for ncu
    k_nop<<<1, 32>>>();
    k_main<<<tg, 256>>>(img);
    k_hi<<<1, 32>>>();
    k_class<<<TOTAL / (256 * 4), 256>>>();
    k_hyst_p<<<hg, 256>>>((float4*)d_out);
}